// round 8
// baseline (speedup 1.0000x reference)
#include <cuda_runtime.h>
#include <cuda_fp16.h>

// Problem constants (fixed by setup_inputs)
static constexpr int N_NODES = 100000;
static constexpr int N_EDGES = 1600000;
static constexpr int SCAN_B  = 512;
static constexpr int SCAN_NB = (N_NODES + SCAN_B - 1) / SCAN_B;  // 196

// ---------------- scratch (static __device__, allocation-free) ----------------
__device__ int   g_cnt[N_NODES];        // degree counts, then reused row base
__device__ int   g_row[N_NODES + 1];    // CSR row offsets
__device__ int   g_blkagg[SCAN_NB];
__device__ volatile int g_blkflag[SCAN_NB];
__device__ int   g_col[N_EDGES];        // CSR: src node per entry
__device__ int   g_pos[N_EDGES];        // edge's position within its dst row
__device__ int2  g_sd[N_EDGES];         // decoded (src,dst) per edge
__device__ float g_dinv[N_NODES];
__device__ float g_t1[N_NODES * 16];    // dinv * (x @ W1)
__device__ float g_h1[N_NODES * 16];    // dinv * relu(...)   (pre-scaled)
__device__ unsigned int g_h2h[N_NODES * 32];  // fp16 half2: dinv * relu(a2@W2+b2)
__device__ float g_a3[N_NODES * 64];    // dinv * sum
__device__ int   g_is64;

// ---------------- f32x2 packed-FMA helpers (sm_103a) ----------------
typedef unsigned long long ull;
__device__ __forceinline__ ull pack2(float v) {
    ull r; asm("mov.b64 %0, {%1, %1};" : "=l"(r) : "f"(v)); return r;
}
__device__ __forceinline__ void ffma2(ull& d, ull a, ull b) {
    asm("fma.rn.f32x2 %0, %1, %2, %0;" : "+l"(d) : "l"(a), "l"(b));
}
__device__ __forceinline__ float2 unpack2(ull v) {
    float2 r; asm("mov.b64 {%0, %1}, %2;" : "=f"(r.x), "=f"(r.y) : "l"(v)); return r;
}

// ---------------- graph build ----------------
__global__ void k_init(const unsigned int* __restrict__ e) {
    int i = blockIdx.x * blockDim.x + threadIdx.x;
    if (i < N_NODES) g_cnt[i] = 0;
    if (i < SCAN_NB) g_blkflag[i] = 0;
    if (i == 0) {
        int is64 = 1;
        for (int k = 0; k < 64; k++) {
            if (e[2 * k + 1] != 0u) { is64 = 0; break; }
        }
        g_is64 = is64;
    }
}

// decode once, count degree; atomic return value IS the within-row position
__global__ void k_count(const void* e) {
    int i = blockIdx.x * blockDim.x + threadIdx.x;
    if (i >= N_EDGES) return;
    int s, d;
    if (g_is64) {
        const long long* p = (const long long*)e;
        s = (int)p[i];
        d = (int)p[N_EDGES + i];
    } else {
        const int* p = (const int*)e;
        s = p[i];
        d = p[N_EDGES + i];
    }
    if ((unsigned)d >= (unsigned)N_NODES || (unsigned)s >= (unsigned)N_NODES) {
        g_sd[i] = make_int2(0, -1);   // marker: skip in fill
        return;
    }
    g_pos[i] = atomicAdd(&g_cnt[d], 1);
    g_sd[i]  = make_int2(s, d);
}

// single-kernel exclusive scan (aggregate publish + spin on earlier blocks).
// All 196 blocks resident in wave 1, so spinning cannot deadlock.
__global__ void __launch_bounds__(SCAN_B) k_scan() {
    __shared__ int s[SCAN_B];
    __shared__ int sPre;
    int bid = blockIdx.x;
    int i = bid * SCAN_B + threadIdx.x;
    int v = (i < N_NODES) ? g_cnt[i] : 0;
    if (i < N_NODES) g_dinv[i] = rsqrtf((float)(v + 1));
    s[threadIdx.x] = v;
    __syncthreads();
    for (int d = 1; d < SCAN_B; d <<= 1) {
        int t = (threadIdx.x >= d) ? s[threadIdx.x - d] : 0;
        __syncthreads();
        s[threadIdx.x] += t;
        __syncthreads();
    }
    if (threadIdx.x == SCAN_B - 1) {
        g_blkagg[bid] = s[SCAN_B - 1];
        __threadfence();
        g_blkflag[bid] = 1;
    }
    if (threadIdx.x == 0) sPre = 0;
    __syncthreads();
    int p = 0;
    for (int b = threadIdx.x; b < bid; b += SCAN_B) {
        while (g_blkflag[b] == 0) { }
        p += *((volatile int*)&g_blkagg[b]);
    }
    if (p) atomicAdd(&sPre, p);
    __syncthreads();
    int prefix = sPre;
    if (i < N_NODES) g_row[i] = prefix + s[threadIdx.x] - v;   // exclusive
    if (bid == 0 && threadIdx.x == 0) g_row[N_NODES] = N_EDGES;
}

// atomic-free fill: coalesced reads, one scattered row-base read, one 4B store
__global__ void k_fill() {
    int i = blockIdx.x * blockDim.x + threadIdx.x;
    if (i >= N_EDGES) return;
    int2 sd = g_sd[i];
    if (sd.y < 0) return;
    g_col[g_row[sd.y] + g_pos[i]] = sd.x;
}

// ---------------- layer 1 GEMM: t1' = dinv ⊙ (x @ W1)  (f32x2) -----------------
__global__ void __launch_bounds__(256) k_gemm1(const float* __restrict__ x,
                                               const float* __restrict__ W1) {
    __shared__ __align__(16) float sW[128 * 16];
    for (int idx = threadIdx.x; idx < 128 * 16; idx += 256) sW[idx] = W1[idx];
    __syncthreads();
    int n = blockIdx.x * 256 + threadIdx.x;
    if (n >= N_NODES) return;
    const float4* xr = (const float4*)(x + (size_t)n * 128);
    ull acc[8];
#pragma unroll
    for (int q = 0; q < 8; q++) acc[q] = 0ull;
#pragma unroll 4
    for (int k4 = 0; k4 < 32; k4++) {
        float4 v = __ldg(&xr[k4]);
#pragma unroll
        for (int kk = 0; kk < 4; kk++) {
            float xv = (kk == 0) ? v.x : (kk == 1) ? v.y : (kk == 2) ? v.z : v.w;
            ull av = pack2(xv);
            const ulonglong2* wr = (const ulonglong2*)(sW + (4 * k4 + kk) * 16);
            ulonglong2 w01 = wr[0], w23 = wr[1], w45 = wr[2], w67 = wr[3];
            ffma2(acc[0], av, w01.x); ffma2(acc[1], av, w01.y);
            ffma2(acc[2], av, w23.x); ffma2(acc[3], av, w23.y);
            ffma2(acc[4], av, w45.x); ffma2(acc[5], av, w45.y);
            ffma2(acc[6], av, w67.x); ffma2(acc[7], av, w67.y);
        }
    }
    float di = g_dinv[n];
    float4* o = (float4*)(g_t1 + (size_t)n * 16);
#pragma unroll
    for (int q = 0; q < 4; q++) {
        float2 p0 = unpack2(acc[2 * q]), p1 = unpack2(acc[2 * q + 1]);
        o[q] = make_float4(di * p0.x, di * p0.y, di * p1.x, di * p1.y);
    }
}

// ---------------- agg 16-wide (+b1+relu): h1' = relu(di²·S + di·b1) ------------
__global__ void __launch_bounds__(256) k_agg16(const float* __restrict__ bias) {
    const float4* __restrict__ t4 = (const float4*)g_t1;
    float4* __restrict__ o4 = (float4*)g_h1;
    int g = threadIdx.x & 3;
    int i = blockIdx.x * 64 + (threadIdx.x >> 2);
    if (i >= N_NODES) return;

    float4 acc = t4[(size_t)i * 4 + g];  // self loop
    int beg = g_row[i], end = g_row[i + 1];
    int j = beg;
    for (; j + 3 < end; j += 4) {
        int s0 = __ldg(&g_col[j]);
        int s1 = __ldg(&g_col[j + 1]);
        int s2 = __ldg(&g_col[j + 2]);
        int s3 = __ldg(&g_col[j + 3]);
        float4 v0 = __ldg(&t4[(size_t)s0 * 4 + g]);
        float4 v1 = __ldg(&t4[(size_t)s1 * 4 + g]);
        float4 v2 = __ldg(&t4[(size_t)s2 * 4 + g]);
        float4 v3 = __ldg(&t4[(size_t)s3 * 4 + g]);
        acc.x += (v0.x + v1.x) + (v2.x + v3.x);
        acc.y += (v0.y + v1.y) + (v2.y + v3.y);
        acc.z += (v0.z + v1.z) + (v2.z + v3.z);
        acc.w += (v0.w + v1.w) + (v2.w + v3.w);
    }
    for (; j < end; j++) {
        int s = __ldg(&g_col[j]);
        float4 v = __ldg(&t4[(size_t)s * 4 + g]);
        acc.x += v.x; acc.y += v.y; acc.z += v.z; acc.w += v.w;
    }
    float di = g_dinv[i];
    float4 b = ((const float4*)bias)[g];
    float d2 = di * di;
    float4 r;
    r.x = fmaxf(fmaf(d2, acc.x, di * b.x), 0.f);
    r.y = fmaxf(fmaf(d2, acc.y, di * b.y), 0.f);
    r.z = fmaxf(fmaf(d2, acc.z, di * b.z), 0.f);
    r.w = fmaxf(fmaf(d2, acc.w, di * b.w), 0.f);
    o4[(size_t)i * 4 + g] = r;
}

// ---------------- fused: agg(h1) 16-wide -> GEMM 16->64 -> fp16 h2' ------------
// 4 threads/node: each aggregates a float4 slice, quad-shuffles to share all 16
// a-values, then computes 16 of the 64 outputs (8 f32x2), writes fp16 row.
__global__ void __launch_bounds__(256) k_aggemm2(const float* __restrict__ W2,
                                                 const float* __restrict__ b2) {
    __shared__ __align__(16) float sW[16 * 64];
    __shared__ __align__(16) float sB[64];
    for (int idx = threadIdx.x; idx < 16 * 64; idx += 256) sW[idx] = W2[idx];
    if (threadIdx.x < 64) sB[threadIdx.x] = b2[threadIdx.x];
    __syncthreads();

    const float4* __restrict__ t4 = (const float4*)g_h1;
    int g = threadIdx.x & 3;
    int i = blockIdx.x * 64 + (threadIdx.x >> 2);
    if (i >= N_NODES) return;

    float4 acc = t4[(size_t)i * 4 + g];
    int beg = g_row[i], end = g_row[i + 1];
    int j = beg;
    for (; j + 3 < end; j += 4) {
        int s0 = __ldg(&g_col[j]);
        int s1 = __ldg(&g_col[j + 1]);
        int s2 = __ldg(&g_col[j + 2]);
        int s3 = __ldg(&g_col[j + 3]);
        float4 v0 = __ldg(&t4[(size_t)s0 * 4 + g]);
        float4 v1 = __ldg(&t4[(size_t)s1 * 4 + g]);
        float4 v2 = __ldg(&t4[(size_t)s2 * 4 + g]);
        float4 v3 = __ldg(&t4[(size_t)s3 * 4 + g]);
        acc.x += (v0.x + v1.x) + (v2.x + v3.x);
        acc.y += (v0.y + v1.y) + (v2.y + v3.y);
        acc.z += (v0.z + v1.z) + (v2.z + v3.z);
        acc.w += (v0.w + v1.w) + (v2.w + v3.w);
    }
    for (; j < end; j++) {
        int s = __ldg(&g_col[j]);
        float4 v = __ldg(&t4[(size_t)s * 4 + g]);
        acc.x += v.x; acc.y += v.y; acc.z += v.z; acc.w += v.w;
    }
    float di = g_dinv[i];
    // a2 slice owned by this thread
    float4 mya = make_float4(di * acc.x, di * acc.y, di * acc.z, di * acc.w);

    // quad-shuffle: gather all 16 a-values
    float a[16];
    int base = threadIdx.x & 31 & ~3;   // quad base lane within warp
#pragma unroll
    for (int q = 0; q < 4; q++) {
        int src = base + q;
        a[4 * q + 0] = __shfl_sync(0xffffffffu, mya.x, src);
        a[4 * q + 1] = __shfl_sync(0xffffffffu, mya.y, src);
        a[4 * q + 2] = __shfl_sync(0xffffffffu, mya.z, src);
        a[4 * q + 3] = __shfl_sync(0xffffffffu, mya.w, src);
    }

    // this thread computes outputs j = g*16 .. g*16+15  (8 f32x2 accumulators)
    ull oacc[8];
    const ull* sBu = (const ull*)sB;
#pragma unroll
    for (int m = 0; m < 8; m++) oacc[m] = sBu[g * 8 + m];
#pragma unroll
    for (int k = 0; k < 16; k++) {
        ull av = pack2(a[k]);
        const ull* wr = (const ull*)(sW + k * 64) + g * 8;
#pragma unroll
        for (int m = 0; m < 8; m++) ffma2(oacc[m], av, wr[m]);
    }
    unsigned int hs[8];
#pragma unroll
    for (int m = 0; m < 8; m++) {
        float2 pv = unpack2(oacc[m]);
        __half2 h = __floats2half2_rn(fmaxf(di * pv.x, 0.f), fmaxf(di * pv.y, 0.f));
        hs[m] = *(const unsigned int*)&h;
    }
    uint4* o = (uint4*)(g_h2h + (size_t)i * 32 + g * 8);
    o[0] = make_uint4(hs[0], hs[1], hs[2], hs[3]);
    o[1] = make_uint4(hs[4], hs[5], hs[6], hs[7]);
}

// ---------------- fp16 aggregation (64-wide): a3 = di·(h2'[i] + Σ h2'[src]) ----
__global__ void __launch_bounds__(256) k_agg64h() {
    const uint2* __restrict__ t = (const uint2*)g_h2h;  // 16 uint2 per node
    int g = threadIdx.x & 15;
    int i = blockIdx.x * 16 + (threadIdx.x >> 4);
    if (i >= N_NODES) return;

    uint2 sv = __ldg(&t[(size_t)i * 16 + g]);
    float2 lo = __half22float2(*(const __half2*)&sv.x);
    float2 hi = __half22float2(*(const __half2*)&sv.y);
    float4 acc = make_float4(lo.x, lo.y, hi.x, hi.y);

    int beg = g_row[i], end = g_row[i + 1];
    int j = beg;
    for (; j + 3 < end; j += 4) {
        int s0 = __ldg(&g_col[j]);
        int s1 = __ldg(&g_col[j + 1]);
        int s2 = __ldg(&g_col[j + 2]);
        int s3 = __ldg(&g_col[j + 3]);
        uint2 v0 = __ldg(&t[(size_t)s0 * 16 + g]);
        uint2 v1 = __ldg(&t[(size_t)s1 * 16 + g]);
        uint2 v2 = __ldg(&t[(size_t)s2 * 16 + g]);
        uint2 v3 = __ldg(&t[(size_t)s3 * 16 + g]);
        float2 a0 = __half22float2(*(const __half2*)&v0.x), b0 = __half22float2(*(const __half2*)&v0.y);
        float2 a1 = __half22float2(*(const __half2*)&v1.x), b1 = __half22float2(*(const __half2*)&v1.y);
        float2 a2 = __half22float2(*(const __half2*)&v2.x), b2 = __half22float2(*(const __half2*)&v2.y);
        float2 a3 = __half22float2(*(const __half2*)&v3.x), b3 = __half22float2(*(const __half2*)&v3.y);
        acc.x += (a0.x + a1.x) + (a2.x + a3.x);
        acc.y += (a0.y + a1.y) + (a2.y + a3.y);
        acc.z += (b0.x + b1.x) + (b2.x + b3.x);
        acc.w += (b0.y + b1.y) + (b2.y + b3.y);
    }
    for (; j < end; j++) {
        int s = __ldg(&g_col[j]);
        uint2 v = __ldg(&t[(size_t)s * 16 + g]);
        float2 a = __half22float2(*(const __half2*)&v.x);
        float2 b = __half22float2(*(const __half2*)&v.y);
        acc.x += a.x; acc.y += a.y; acc.z += b.x; acc.w += b.y;
    }
    float di = g_dinv[i];
    ((float4*)g_a3)[(size_t)i * 16 + g] =
        make_float4(di * acc.x, di * acc.y, di * acc.z, di * acc.w);
}

// ---------------- fused layer 3 + FC (f32x2):
// out[n] = Σ_j relu( a3[n,:]·W3[:,j] + b3[j] ) * Wfc[j] + bfc
__global__ void __launch_bounds__(256) k_final(const float* __restrict__ W3,
                                               const float* __restrict__ b3,
                                               const float* __restrict__ Wfc,
                                               const float* __restrict__ bfc,
                                               float* __restrict__ out) {
    __shared__ __align__(16) float sW[64 * 128];   // 32KB
    __shared__ __align__(16) float sB[128];
    __shared__ __align__(16) float sF[128];
    for (int idx = threadIdx.x; idx < 64 * 128; idx += 256) sW[idx] = W3[idx];
    if (threadIdx.x < 128) {
        sB[threadIdx.x] = b3[threadIdx.x];
        sF[threadIdx.x] = Wfc[threadIdx.x];
    }
    __syncthreads();
    int n = blockIdx.x * 256 + threadIdx.x;
    if (n >= N_NODES) return;

    float a[64];
    const float4* ar = (const float4*)(g_a3 + (size_t)n * 64);
#pragma unroll
    for (int k4 = 0; k4 < 16; k4++) {
        float4 v = __ldg(&ar[k4]);
        a[4 * k4 + 0] = v.x; a[4 * k4 + 1] = v.y;
        a[4 * k4 + 2] = v.z; a[4 * k4 + 3] = v.w;
    }

    float o = 0.f;
#pragma unroll 1
    for (int j = 0; j < 128; j += 8) {
        const ulonglong2* bi = (const ulonglong2*)(sB + j);
        ulonglong2 b01 = bi[0], b23 = bi[1];
        ull acc0 = b01.x, acc1 = b01.y, acc2 = b23.x, acc3 = b23.y;
#pragma unroll
        for (int k = 0; k < 64; k++) {
            ull av = pack2(a[k]);
            const ulonglong2* w = (const ulonglong2*)(sW + k * 128 + j);
            ulonglong2 w01 = w[0], w23 = w[1];
            ffma2(acc0, av, w01.x);
            ffma2(acc1, av, w01.y);
            ffma2(acc2, av, w23.x);
            ffma2(acc3, av, w23.y);
        }
        float2 p0 = unpack2(acc0), p1 = unpack2(acc1);
        float2 p2 = unpack2(acc2), p3 = unpack2(acc3);
        o += fmaxf(p0.x, 0.f) * sF[j + 0] + fmaxf(p0.y, 0.f) * sF[j + 1];
        o += fmaxf(p1.x, 0.f) * sF[j + 2] + fmaxf(p1.y, 0.f) * sF[j + 3];
        o += fmaxf(p2.x, 0.f) * sF[j + 4] + fmaxf(p2.y, 0.f) * sF[j + 5];
        o += fmaxf(p3.x, 0.f) * sF[j + 6] + fmaxf(p3.y, 0.f) * sF[j + 7];
    }
    out[n] = o + bfc[0];
}

// ---------------- launch ----------------
extern "C" void kernel_launch(void* const* d_in, const int* in_sizes, int n_in,
                              void* d_out, int out_size) {
    const float* x   = (const float*)d_in[0];
    const void*  ei  = d_in[1];
    const float* W1  = (const float*)d_in[2];
    const float* b1  = (const float*)d_in[3];
    const float* W2  = (const float*)d_in[4];
    const float* b2  = (const float*)d_in[5];
    const float* W3  = (const float*)d_in[6];
    const float* b3  = (const float*)d_in[7];
    const float* Wfc = (const float*)d_in[8];
    const float* bfc = (const float*)d_in[9];
    float* out = (float*)d_out;

    const int TB = 256;
    const int gN = (N_NODES + TB - 1) / TB;
    const int gE = (N_EDGES + TB - 1) / TB;

    // graph construction: count(+pos) -> one-kernel scan -> atomic-free fill
    k_init<<<gN, TB>>>((const unsigned int*)ei);
    k_count<<<gE, TB>>>(ei);
    k_scan<<<SCAN_NB, SCAN_B>>>();
    k_fill<<<gE, TB>>>();

    // layer 1: GEMM (128->16, pre-scaled) then aggregate 16-wide (+b1+relu)
    k_gemm1<<<gN, TB>>>(x, W1);
    k_agg16<<<(N_NODES * 4 + TB - 1) / TB, TB>>>(b1);

    // layer 2: fused aggregate(16) + GEMM 16->64 -> fp16 h2'
    k_aggemm2<<<(N_NODES * 4 + TB - 1) / TB, TB>>>(W2, b2);

    // layer 3: fp16 aggregate 64-wide, then fused GEMM 64->128 + relu + FC
    k_agg64h<<<(N_NODES * 16 + TB - 1) / TB, TB>>>();
    k_final<<<gN, TB>>>(W3, b3, Wfc, bfc, out);
}